// round 2
// baseline (speedup 1.0000x reference)
#include <cuda_runtime.h>

#define NUSERS 100000
#define NITEMS 50000
#define NNODES 150000
#define NEDGES 4000000
#define HDIM   64
#define NBATCH 100000
#define NHID   32

// Scratch (device-global: allocation-free per harness rules)
__device__ float g_XA[NNODES * HDIM];
__device__ float g_XB[NNODES * HDIM];
__device__ float g_SUM[NNODES * HDIM];
__device__ int   g_cnt[NNODES];
__device__ float g_inv[NNODES];

// ---------------------------------------------------------------------------
// inv[n] = 1/max(cnt[n],1)
// ---------------------------------------------------------------------------
__global__ void inv_kernel() {
    int n = blockIdx.x * blockDim.x + threadIdx.x;
    if (n < NNODES) g_inv[n] = 1.0f / (float)max(g_cnt[n], 1);
}

// ---------------------------------------------------------------------------
// x0 = concat(user_emb, item_emb)
// ---------------------------------------------------------------------------
__global__ void init_x(const float4* __restrict__ ue, const float4* __restrict__ ie) {
    int i = blockIdx.x * blockDim.x + threadIdx.x;
    const int UQ = NUSERS * HDIM / 4;
    const int NQ = NNODES * HDIM / 4;
    if (i < UQ)      ((float4*)g_XA)[i] = ue[i];
    else if (i < NQ) ((float4*)g_XA)[i] = ie[i - UQ];
}

// ---------------------------------------------------------------------------
// Scatter-add: SUM[dst] += X[src]. 16 threads per edge, one float4 each.
// Vectorized red.global.add.v4.f32 (sm_90+): 1 atomic per 16B.
// COUNT: fuse the degree histogram into the layer-0 pass (lane c==0).
// ---------------------------------------------------------------------------
template <bool COUNT>
__global__ void scatter_kernel(const int* __restrict__ src, const int* __restrict__ dst,
                               const float* __restrict__ Xin) {
    unsigned idx = blockIdx.x * blockDim.x + threadIdx.x;
    unsigned e = idx >> 4;
    int c = idx & 15;
    if (e >= NEDGES) return;
    int s = __ldg(src + e);
    int d = __ldg(dst + e);
    if (COUNT && c == 0) atomicAdd(&g_cnt[d], 1);
    float4 v = __ldg((const float4*)(Xin + (size_t)s * HDIM) + c);
    float* p = g_SUM + (size_t)d * HDIM + c * 4;
    asm volatile("red.global.add.v4.f32 [%0], {%1,%2,%3,%4};"
                 :: "l"(p), "f"(v.x), "f"(v.y), "f"(v.z), "f"(v.w)
                 : "memory");
}

// ---------------------------------------------------------------------------
// Xout[n] = relu( (SUM[n]*inv[n]) @ Wl + Xin[n] @ Wr + bl )
// 256 threads = 4 node-groups x 64 output features; 32 nodes per block.
// W columns register-cached per thread; node rows via float4 smem broadcast.
// ---------------------------------------------------------------------------
__global__ void __launch_bounds__(256)
sage_kernel(const float* __restrict__ Xin, float* __restrict__ Xout,
            const float* __restrict__ Wl, const float* __restrict__ bl,
            const float* __restrict__ Wr) {
    __shared__ __align__(16) float mrow[4][HDIM];
    __shared__ __align__(16) float xrow[4][HDIM];
    int tid = threadIdx.x;
    int g = tid >> 6, j = tid & 63;

    float wlc[HDIM], wrc[HDIM];
#pragma unroll
    for (int k = 0; k < HDIM; ++k) {
        wlc[k] = __ldg(Wl + k * HDIM + j);
        wrc[k] = __ldg(Wr + k * HDIM + j);
    }
    float bj = __ldg(bl + j);

    int base = blockIdx.x * 32;
#pragma unroll 1
    for (int it = 0; it < 8; ++it) {
        int n = base + it * 4 + g;
        bool ok = (n < NNODES);
        if (ok) {
            float inv = g_inv[n];
            mrow[g][j] = g_SUM[(size_t)n * HDIM + j] * inv;
            xrow[g][j] = Xin[(size_t)n * HDIM + j];
        }
        __syncthreads();
        if (ok) {
            float acc = bj;
            const float4* m4 = (const float4*)mrow[g];
            const float4* x4 = (const float4*)xrow[g];
#pragma unroll
            for (int k4 = 0; k4 < HDIM / 4; ++k4) {
                float4 m = m4[k4], x = x4[k4];
                acc = fmaf(m.x, wlc[4 * k4 + 0], acc);
                acc = fmaf(m.y, wlc[4 * k4 + 1], acc);
                acc = fmaf(m.z, wlc[4 * k4 + 2], acc);
                acc = fmaf(m.w, wlc[4 * k4 + 3], acc);
                acc = fmaf(x.x, wrc[4 * k4 + 0], acc);
                acc = fmaf(x.y, wrc[4 * k4 + 1], acc);
                acc = fmaf(x.z, wrc[4 * k4 + 2], acc);
                acc = fmaf(x.w, wrc[4 * k4 + 3], acc);
            }
            Xout[(size_t)n * HDIM + j] = fmaxf(acc, 0.0f);
        }
        __syncthreads();
    }
}

// ---------------------------------------------------------------------------
// Final MLP + clip. One warp per pair; lane = hidden unit (NHID==32).
// ---------------------------------------------------------------------------
__global__ void __launch_bounds__(256)
mlp_kernel(const float* __restrict__ X,
           const int* __restrict__ uid, const int* __restrict__ iid,
           const float* __restrict__ W1, const float* __restrict__ b1,
           const float* __restrict__ W2, const float* __restrict__ b2,
           float* __restrict__ out) {
    __shared__ float sW1[2 * HDIM * NHID];
    __shared__ float sb1[NHID], sW2[NHID];
    int tid = threadIdx.x;
    for (int i = tid; i < 2 * HDIM * NHID; i += 256) sW1[i] = W1[i];
    if (tid < NHID) { sb1[tid] = b1[tid]; sW2[tid] = W2[tid]; }
    __syncthreads();

    int warp = tid >> 5, lane = tid & 31;
    int pair = blockIdx.x * 8 + warp;
    if (pair >= NBATCH) return;

    const float* ue = X + (size_t)__ldg(uid + pair) * HDIM;
    const float* ie = X + ((size_t)__ldg(iid + pair) + NUSERS) * HDIM;

    float acc = sb1[lane];
#pragma unroll
    for (int k = 0; k < HDIM; ++k)
        acc = fmaf(__ldg(ue + k), sW1[k * NHID + lane], acc);
#pragma unroll
    for (int k = 0; k < HDIM; ++k)
        acc = fmaf(__ldg(ie + k), sW1[(HDIM + k) * NHID + lane], acc);

    float r = fmaxf(acc, 0.0f) * sW2[lane];
#pragma unroll
    for (int off = 16; off; off >>= 1)
        r += __shfl_xor_sync(0xffffffffu, r, off);

    if (lane == 0) {
        r += __ldg(b2);
        out[pair] = fminf(fmaxf(r, 1.0f), 5.0f);
    }
}

// ---------------------------------------------------------------------------
extern "C" void kernel_launch(void* const* d_in, const int* in_sizes, int n_in,
                              void* d_out, int out_size) {
    const int*   edge     = (const int*)d_in[0];
    const int*   src      = edge;
    const int*   dst      = edge + NEDGES;
    const int*   user_ids = (const int*)d_in[1];
    const int*   item_ids = (const int*)d_in[2];
    const float* user_emb = (const float*)d_in[3];
    const float* item_emb = (const float*)d_in[4];
    const float* Wl       = (const float*)d_in[5];
    const float* bl       = (const float*)d_in[6];
    const float* Wr       = (const float*)d_in[7];
    const float* W1       = (const float*)d_in[8];
    const float* b1       = (const float*)d_in[9];
    const float* W2       = (const float*)d_in[10];
    const float* b2       = (const float*)d_in[11];

    void *pSum, *pCnt, *pXA, *pXB;
    cudaGetSymbolAddress(&pSum, g_SUM);
    cudaGetSymbolAddress(&pCnt, g_cnt);
    cudaGetSymbolAddress(&pXA, g_XA);
    cudaGetSymbolAddress(&pXB, g_XB);

    // x0 = concat(user_emb, item_emb)
    init_x<<<(NNODES * HDIM / 4 + 255) / 256, 256>>>(
        (const float4*)user_emb, (const float4*)item_emb);

    cudaMemsetAsync(pCnt, 0, NNODES * sizeof(int));

    float* bufs[2] = {(float*)pXA, (float*)pXB};
    for (int l = 0; l < 3; ++l) {
        cudaMemsetAsync(pSum, 0, (size_t)NNODES * HDIM * sizeof(float));
        if (l == 0) {
            // Fused: degree histogram + first scatter in one pass over edges.
            scatter_kernel<true><<<(NEDGES * 16) / 256, 256>>>(src, dst, bufs[0]);
            inv_kernel<<<(NNODES + 255) / 256, 256>>>();
        } else {
            scatter_kernel<false><<<(NEDGES * 16) / 256, 256>>>(src, dst, bufs[l & 1]);
        }
        sage_kernel<<<(NNODES + 31) / 32, 256>>>(
            bufs[l & 1], bufs[(l + 1) & 1],
            Wl + l * HDIM * HDIM, bl + l * HDIM, Wr + l * HDIM * HDIM);
    }

    mlp_kernel<<<(NBATCH + 7) / 8, 256>>>(
        bufs[1], user_ids, item_ids, W1, b1, W2, b2, (float*)d_out);
}

// round 13
// speedup vs baseline: 1.8918x; 1.8918x over previous
#include <cuda_runtime.h>

#define NUSERS 100000
#define NITEMS 50000
#define NNODES 150000
#define NEDGES 4000000
#define HDIM   64
#define NBATCH 100000
#define NHID   32

// Scratch (device-global: allocation-free per harness rules)
__device__ float g_XA[NNODES * HDIM];
__device__ float g_XB[NNODES * HDIM];
__device__ float g_MEAN[NNODES * HDIM];
__device__ int   g_cnt[NNODES];
__device__ int   g_off[NNODES + 1];
__device__ int   g_cursor[NNODES];
__device__ int   g_ssrc[NEDGES];

// ---------------------------------------------------------------------------
// x0 = concat(user_emb, item_emb)
// ---------------------------------------------------------------------------
__global__ void init_x(const float4* __restrict__ ue, const float4* __restrict__ ie) {
    int i = blockIdx.x * blockDim.x + threadIdx.x;
    const int UQ = NUSERS * HDIM / 4;
    const int NQ = NNODES * HDIM / 4;
    if (i < UQ)      ((float4*)g_XA)[i] = ue[i];
    else if (i < NQ) ((float4*)g_XA)[i] = ie[i - UQ];
}

// ---------------------------------------------------------------------------
// Counting sort of edges by dst (dst is loop-invariant: done once).
// ---------------------------------------------------------------------------
__global__ void count_kernel(const int* __restrict__ dst) {
    int e = blockIdx.x * blockDim.x + threadIdx.x;
    if (e < NEDGES) atomicAdd(&g_cnt[dst[e]], 1);
}

// Single-block exclusive scan over 150k counts -> g_off, g_cursor.
__global__ void __launch_bounds__(1024) scan_kernel() {
    __shared__ int ssum[1024];
    int t = threadIdx.x;
    const int CH = (NNODES + 1023) / 1024;   // 147
    int begin = t * CH;
    int end = min(begin + CH, NNODES);
    int s = 0;
    for (int i = begin; i < end; ++i) s += g_cnt[i];
    ssum[t] = s;
    __syncthreads();
    // inclusive scan (Hillis-Steele)
    for (int d = 1; d < 1024; d <<= 1) {
        int v = 0;
        if (t >= d) v = ssum[t - d];
        __syncthreads();
        ssum[t] += v;
        __syncthreads();
    }
    int off = (t == 0) ? 0 : ssum[t - 1];
    for (int i = begin; i < end; ++i) {
        g_off[i] = off;
        g_cursor[i] = off;
        off += g_cnt[i];
    }
    if (t == 1023) g_off[NNODES] = NEDGES;
}

__global__ void reorder_kernel(const int* __restrict__ src, const int* __restrict__ dst) {
    int e = blockIdx.x * blockDim.x + threadIdx.x;
    if (e >= NEDGES) return;
    int pos = atomicAdd(&g_cursor[dst[e]], 1);
    g_ssrc[pos] = src[e];
}

// ---------------------------------------------------------------------------
// Segmented gather-reduce: MEAN[n] = (1/max(deg,1)) * sum_{e in seg(n)} X[ssrc[e]]
// 16 threads per node, each owns one float4 column. No atomics, no memset.
// 2-edge batching + dual accumulators for memory-level parallelism.
// ---------------------------------------------------------------------------
__global__ void __launch_bounds__(256)
agg_kernel(const float* __restrict__ Xin) {
    unsigned idx = blockIdx.x * blockDim.x + threadIdx.x;
    unsigned n = idx >> 4;
    int c = idx & 15;
    if (n >= NNODES) return;
    int s0 = __ldg(g_off + n);
    int s1 = __ldg(g_off + n + 1);
    float4 a0 = make_float4(0.f, 0.f, 0.f, 0.f);
    float4 a1 = make_float4(0.f, 0.f, 0.f, 0.f);
    int e = s0;
    for (; e + 2 <= s1; e += 2) {
        int sA = __ldg(g_ssrc + e);
        int sB = __ldg(g_ssrc + e + 1);
        float4 vA = __ldg((const float4*)(Xin + (size_t)sA * HDIM) + c);
        float4 vB = __ldg((const float4*)(Xin + (size_t)sB * HDIM) + c);
        a0.x += vA.x; a0.y += vA.y; a0.z += vA.z; a0.w += vA.w;
        a1.x += vB.x; a1.y += vB.y; a1.z += vB.z; a1.w += vB.w;
    }
    if (e < s1) {
        int sA = __ldg(g_ssrc + e);
        float4 vA = __ldg((const float4*)(Xin + (size_t)sA * HDIM) + c);
        a0.x += vA.x; a0.y += vA.y; a0.z += vA.z; a0.w += vA.w;
    }
    float inv = 1.0f / (float)max(s1 - s0, 1);
    float4 acc;
    acc.x = (a0.x + a1.x) * inv;
    acc.y = (a0.y + a1.y) * inv;
    acc.z = (a0.z + a1.z) * inv;
    acc.w = (a0.w + a1.w) * inv;
    ((float4*)(g_MEAN + (size_t)n * HDIM))[c] = acc;
}

// ---------------------------------------------------------------------------
// SAGE linear v2: register-tiled smem GEMM.
// Block = 256 threads, tile = 64 nodes x 64 outputs, 16 f32 accs/thread.
// Xout[n] = relu( MEAN[n] @ Wl + Xin[n] @ Wr + bl )
// ---------------------------------------------------------------------------
__global__ void __launch_bounds__(256, 2)
sage_kernel(const float* __restrict__ Xin, float* __restrict__ Xout,
            const float* __restrict__ Wl, const float* __restrict__ bl,
            const float* __restrict__ Wr) {
    __shared__ __align__(16) float4 sW[2][HDIM][16];    // [mat][k][j4]    32 KB
    __shared__ __align__(16) float4 sRow[2][64][16];    // [mat][node][k4] 32 KB

    int tid = threadIdx.x;
    int base = blockIdx.x * 64;

    const float4* Wl4 = (const float4*)Wl;
    const float4* Wr4 = (const float4*)Wr;
#pragma unroll
    for (int p = 0; p < 4; ++p) {
        int i = p * 256 + tid;
        sW[0][i >> 4][i & 15] = __ldg(Wl4 + i);
        sW[1][i >> 4][i & 15] = __ldg(Wr4 + i);
    }
#pragma unroll
    for (int p = 0; p < 4; ++p) {
        int i = p * 256 + tid;
        int r = i >> 4, c = i & 15;
        int n = base + r;
        if (n < NNODES) {
            sRow[0][r][c] = __ldg((const float4*)(g_MEAN + (size_t)n * HDIM) + c);
            sRow[1][r][c] = __ldg((const float4*)(Xin + (size_t)n * HDIM) + c);
        }
    }
    __syncthreads();

    int jq = tid & 15, nq = tid >> 4;
    float4 bj = __ldg((const float4*)bl + jq);
    float4 acc[4];
#pragma unroll
    for (int t = 0; t < 4; ++t) acc[t] = bj;

#pragma unroll 4
    for (int k4 = 0; k4 < 16; ++k4) {
        float4 wl0 = sW[0][4 * k4 + 0][jq];
        float4 wl1 = sW[0][4 * k4 + 1][jq];
        float4 wl2 = sW[0][4 * k4 + 2][jq];
        float4 wl3 = sW[0][4 * k4 + 3][jq];
        float4 wr0 = sW[1][4 * k4 + 0][jq];
        float4 wr1 = sW[1][4 * k4 + 1][jq];
        float4 wr2 = sW[1][4 * k4 + 2][jq];
        float4 wr3 = sW[1][4 * k4 + 3][jq];
#pragma unroll
        for (int t = 0; t < 4; ++t) {
            float4 m = sRow[0][nq + 16 * t][k4];
            float4 x = sRow[1][nq + 16 * t][k4];
            acc[t].x = fmaf(m.x, wl0.x, acc[t].x); acc[t].x = fmaf(m.y, wl1.x, acc[t].x);
            acc[t].x = fmaf(m.z, wl2.x, acc[t].x); acc[t].x = fmaf(m.w, wl3.x, acc[t].x);
            acc[t].y = fmaf(m.x, wl0.y, acc[t].y); acc[t].y = fmaf(m.y, wl1.y, acc[t].y);
            acc[t].y = fmaf(m.z, wl2.y, acc[t].y); acc[t].y = fmaf(m.w, wl3.y, acc[t].y);
            acc[t].z = fmaf(m.x, wl0.z, acc[t].z); acc[t].z = fmaf(m.y, wl1.z, acc[t].z);
            acc[t].z = fmaf(m.z, wl2.z, acc[t].z); acc[t].z = fmaf(m.w, wl3.z, acc[t].z);
            acc[t].w = fmaf(m.x, wl0.w, acc[t].w); acc[t].w = fmaf(m.y, wl1.w, acc[t].w);
            acc[t].w = fmaf(m.z, wl2.w, acc[t].w); acc[t].w = fmaf(m.w, wl3.w, acc[t].w);
            acc[t].x = fmaf(x.x, wr0.x, acc[t].x); acc[t].x = fmaf(x.y, wr1.x, acc[t].x);
            acc[t].x = fmaf(x.z, wr2.x, acc[t].x); acc[t].x = fmaf(x.w, wr3.x, acc[t].x);
            acc[t].y = fmaf(x.x, wr0.y, acc[t].y); acc[t].y = fmaf(x.y, wr1.y, acc[t].y);
            acc[t].y = fmaf(x.z, wr2.y, acc[t].y); acc[t].y = fmaf(x.w, wr3.y, acc[t].y);
            acc[t].z = fmaf(x.x, wr0.z, acc[t].z); acc[t].z = fmaf(x.y, wr1.z, acc[t].z);
            acc[t].z = fmaf(x.z, wr2.z, acc[t].z); acc[t].z = fmaf(x.w, wr3.z, acc[t].z);
            acc[t].w = fmaf(x.x, wr0.w, acc[t].w); acc[t].w = fmaf(x.y, wr1.w, acc[t].w);
            acc[t].w = fmaf(x.z, wr2.w, acc[t].w); acc[t].w = fmaf(x.w, wr3.w, acc[t].w);
        }
    }

#pragma unroll
    for (int t = 0; t < 4; ++t) {
        int n = base + nq + 16 * t;
        if (n < NNODES) {
            float4 r;
            r.x = fmaxf(acc[t].x, 0.0f);
            r.y = fmaxf(acc[t].y, 0.0f);
            r.z = fmaxf(acc[t].z, 0.0f);
            r.w = fmaxf(acc[t].w, 0.0f);
            *((float4*)(Xout + (size_t)n * HDIM) + jq) = r;
        }
    }
}

// ---------------------------------------------------------------------------
// Final MLP + clip. One warp per pair; lane = hidden unit (NHID==32).
// ---------------------------------------------------------------------------
__global__ void __launch_bounds__(256)
mlp_kernel(const float* __restrict__ X,
           const int* __restrict__ uid, const int* __restrict__ iid,
           const float* __restrict__ W1, const float* __restrict__ b1,
           const float* __restrict__ W2, const float* __restrict__ b2,
           float* __restrict__ out) {
    __shared__ float sW1[2 * HDIM * NHID];
    __shared__ float sb1[NHID], sW2[NHID];
    int tid = threadIdx.x;
    for (int i = tid; i < 2 * HDIM * NHID; i += 256) sW1[i] = W1[i];
    if (tid < NHID) { sb1[tid] = b1[tid]; sW2[tid] = W2[tid]; }
    __syncthreads();

    int warp = tid >> 5, lane = tid & 31;
    int pair = blockIdx.x * 8 + warp;
    if (pair >= NBATCH) return;

    const float* ue = X + (size_t)__ldg(uid + pair) * HDIM;
    const float* ie = X + ((size_t)__ldg(iid + pair) + NUSERS) * HDIM;

    float acc = sb1[lane];
#pragma unroll
    for (int k = 0; k < HDIM; ++k)
        acc = fmaf(__ldg(ue + k), sW1[k * NHID + lane], acc);
#pragma unroll
    for (int k = 0; k < HDIM; ++k)
        acc = fmaf(__ldg(ie + k), sW1[(HDIM + k) * NHID + lane], acc);

    float r = fmaxf(acc, 0.0f) * sW2[lane];
#pragma unroll
    for (int off = 16; off; off >>= 1)
        r += __shfl_xor_sync(0xffffffffu, r, off);

    if (lane == 0) {
        r += __ldg(b2);
        out[pair] = fminf(fmaxf(r, 1.0f), 5.0f);
    }
}

// ---------------------------------------------------------------------------
extern "C" void kernel_launch(void* const* d_in, const int* in_sizes, int n_in,
                              void* d_out, int out_size) {
    const int*   edge     = (const int*)d_in[0];
    const int*   src      = edge;
    const int*   dst      = edge + NEDGES;
    const int*   user_ids = (const int*)d_in[1];
    const int*   item_ids = (const int*)d_in[2];
    const float* user_emb = (const float*)d_in[3];
    const float* item_emb = (const float*)d_in[4];
    const float* Wl       = (const float*)d_in[5];
    const float* bl       = (const float*)d_in[6];
    const float* Wr       = (const float*)d_in[7];
    const float* W1       = (const float*)d_in[8];
    const float* b1       = (const float*)d_in[9];
    const float* W2       = (const float*)d_in[10];
    const float* b2       = (const float*)d_in[11];

    void *pCnt, *pXA, *pXB;
    cudaGetSymbolAddress(&pCnt, g_cnt);
    cudaGetSymbolAddress(&pXA, g_XA);
    cudaGetSymbolAddress(&pXB, g_XB);

    // x0 = concat(user_emb, item_emb)
    init_x<<<(NNODES * HDIM / 4 + 255) / 256, 256>>>(
        (const float4*)user_emb, (const float4*)item_emb);

    // Counting sort of edges by dst (once; dst invariant across layers)
    cudaMemsetAsync(pCnt, 0, NNODES * sizeof(int));
    count_kernel<<<(NEDGES + 255) / 256, 256>>>(dst);
    scan_kernel<<<1, 1024>>>();
    reorder_kernel<<<(NEDGES + 255) / 256, 256>>>(src, dst);

    float* bufs[2] = {(float*)pXA, (float*)pXB};
    for (int l = 0; l < 3; ++l) {
        agg_kernel<<<(NNODES * 16 + 255) / 256, 256>>>(bufs[l & 1]);
        sage_kernel<<<(NNODES + 63) / 64, 256>>>(
            bufs[l & 1], bufs[(l + 1) & 1],
            Wl + l * HDIM * HDIM, bl + l * HDIM, Wr + l * HDIM * HDIM);
    }

    mlp_kernel<<<(NBATCH + 7) / 8, 256>>>(
        bufs[1], user_ids, item_ids, W1, b1, W2, b2, (float*)d_out);
}